// round 12
// baseline (speedup 1.0000x reference)
#include <cuda_runtime.h>
#include <cuda_bf16.h>
#include <cstdint>
#include <math.h>

#define BATCH   8192
#define D_IN    2048
#define D_HID   16384
#define KSEL    64
#define KAUX    512
#define NCAND   128

// ---------------- scratch ----------------
__device__ float          g_pre[(size_t)BATCH * D_HID];
__device__ float          g_WT[(size_t)D_HID * D_IN];        // fp32 W_dec^T (decode_main)
__device__ uint32_t       g_WTh[(size_t)D_HID * D_IN / 2];   // bf16x2 W_dec^T (decode_aux)
__device__ __nv_bfloat16  g_Xh[(size_t)BATCH * D_IN];        // bf16 split of (x - b_dec)
__device__ __nv_bfloat16  g_Xl[(size_t)BATCH * D_IN];
__device__ __nv_bfloat16  g_Wh[(size_t)D_HID * D_IN];        // bf16 split of W_enc
__device__ __nv_bfloat16  g_Wl[(size_t)D_HID * D_IN];
__device__ int      g_cand[(size_t)BATCH * NCAND];
__device__ int      g_cand_n[BATCH];
__device__ int      g_sel_idx[BATCH * KSEL];
__device__ float    g_sel_val[BATCH * KSEL];
__device__ int      g_aux_idx[(size_t)BATCH * KAUX];
__device__ float    g_aux_val[(size_t)BATCH * KAUX];
__device__ float    g_recon_p[BATCH];
__device__ float    g_aux_p[BATCH];
__device__ float    g_l0_p[BATCH];
__device__ unsigned g_deadbits[D_HID / 32];

// ---------------- helpers ----------------
__device__ __forceinline__ uint32_t f2key(float f) {
    uint32_t u = __float_as_uint(f);
    return (u & 0x80000000u) ? ~u : (u | 0x80000000u);
}
__device__ __forceinline__ float key2f(uint32_t k) {
    uint32_t u = (k & 0x80000000u) ? (k ^ 0x80000000u) : ~k;
    return __uint_as_float(u);
}
__device__ __forceinline__ void mma_bf16(float c[4], uint32_t a0, uint32_t a1,
                                         uint32_t a2, uint32_t a3,
                                         uint32_t b0, uint32_t b1) {
    asm volatile(
        "mma.sync.aligned.m16n8k16.row.col.f32.bf16.bf16.f32 "
        "{%0,%1,%2,%3}, {%4,%5,%6,%7}, {%8,%9}, {%0,%1,%2,%3};\n"
        : "+f"(c[0]), "+f"(c[1]), "+f"(c[2]), "+f"(c[3])
        : "r"(a0), "r"(a1), "r"(a2), "r"(a3), "r"(b0), "r"(b1));
}
__device__ __forceinline__ void ldsm_x4(uint32_t r[4], uint32_t saddr) {
    asm volatile("ldmatrix.sync.aligned.m8n8.x4.shared.b16 {%0,%1,%2,%3}, [%4];"
        : "=r"(r[0]), "=r"(r[1]), "=r"(r[2]), "=r"(r[3]) : "r"(saddr));
}
__device__ __forceinline__ void cp16(uint32_t dst, const void* src) {
    asm volatile("cp.async.cg.shared.global [%0], [%1], 16;" :: "r"(dst), "l"(src));
}
__device__ __forceinline__ uint32_t smem_u32(const void* p) {
    return (uint32_t)__cvta_generic_to_shared(p);
}

// ---------------- dead_mask prep ----------------
__global__ void prep_mask(const uint8_t* __restrict__ m) {
    __shared__ int viol;
    if (threadIdx.x == 0) viol = 0;
    __syncthreads();
    for (int i = threadIdx.x; i < D_HID; i += blockDim.x)
        if ((i & 3) && m[i]) viol = 1;
    __syncthreads();
    const bool is_i32 = (viol == 0);
    const int* mi = (const int*)m;
    for (int w = threadIdx.x; w < D_HID / 32; w += blockDim.x) {
        uint32_t bits = 0;
        #pragma unroll 4
        for (int b = 0; b < 32; ++b) {
            int j = w * 32 + b;
            bool d = is_i32 ? (mi[j] != 0) : (m[j] != 0);
            bits |= ((uint32_t)d) << b;
        }
        g_deadbits[w] = bits;
    }
}

// ---------------- W_dec transpose (fp32) ----------------
__global__ void transpose_wdec(const float* __restrict__ W) {
    __shared__ float t[32][33];
    int x = blockIdx.x * 32 + threadIdx.x;
    int y0 = blockIdx.y * 32;
    #pragma unroll
    for (int i = threadIdx.y; i < 32; i += 8)
        t[i][threadIdx.x] = W[(size_t)(y0 + i) * D_HID + x];
    __syncthreads();
    int xo = y0 + threadIdx.x;
    int yo0 = blockIdx.x * 32;
    #pragma unroll
    for (int i = threadIdx.y; i < 32; i += 8)
        g_WT[(size_t)(yo0 + i) * D_IN + xo] = t[threadIdx.x][i];
}

// ---------------- bf16 conversion of W_dec^T (aux decode) ----------------
__global__ void convert_wdec_bf16() {
    size_t i = (size_t)blockIdx.x * blockDim.x + threadIdx.x;
    if (i < (size_t)D_HID * D_IN / 2) {
        float2 f = *(const float2*)(g_WT + 2 * i);
        __nv_bfloat162 b = __floats2bfloat162_rn(f.x, f.y);
        g_WTh[i] = *reinterpret_cast<uint32_t*>(&b);
    }
}

// ---------------- precompute bf16 hi/lo splits ----------------
__global__ void split_x(const float* __restrict__ X, const float* __restrict__ bd) {
    size_t i = ((size_t)blockIdx.x * blockDim.x + threadIdx.x) * 4;
    if (i < (size_t)BATCH * D_IN) {
        float4 xv = *(const float4*)(X + i);
        float4 dv = *(const float4*)(bd + (i & (D_IN - 1)));
        float v[4] = {xv.x - dv.x, xv.y - dv.y, xv.z - dv.z, xv.w - dv.w};
        __nv_bfloat16 h[4], l[4];
        #pragma unroll
        for (int e = 0; e < 4; ++e) {
            h[e] = __float2bfloat16_rn(v[e]);
            l[e] = __float2bfloat16_rn(v[e] - __bfloat162float(h[e]));
        }
        *(uint2*)(g_Xh + i) = *(uint2*)h;
        *(uint2*)(g_Xl + i) = *(uint2*)l;
    }
}
__global__ void split_w(const float* __restrict__ WE) {
    size_t i = ((size_t)blockIdx.x * blockDim.x + threadIdx.x) * 4;
    if (i < (size_t)D_HID * D_IN) {
        float4 wv = *(const float4*)(WE + i);
        float v[4] = {wv.x, wv.y, wv.z, wv.w};
        __nv_bfloat16 h[4], l[4];
        #pragma unroll
        for (int e = 0; e < 4; ++e) {
            h[e] = __float2bfloat16_rn(v[e]);
            l[e] = __float2bfloat16_rn(v[e] - __bfloat162float(h[e]));
        }
        *(uint2*)(g_Wh + i) = *(uint2*)h;
        *(uint2*)(g_Wl + i) = *(uint2*)l;
    }
}

// ---------------- approx encoder: bf16x2 split m16n8k16, CTA 128x256 ----------------
// 512 threads (4Mx4N warps, warp tile 32x64), BK=32, 3-stage cp.async ring.
// Row stride 80B -> conflict-free ldmatrix. Math identical to R8-R10 (3 products).
#define ENC_BM 128
#define ENC_BN 256
#define ENC_BK 32
#define A_ARR  (128 * 80)                 // 10240 B per A array
#define B_ARR  (256 * 80)                 // 20480 B per B array
#define STG    (2 * A_ARR + 2 * B_ARR)    // 61440 B per stage
#define NTT    (D_IN / ENC_BK)            // 64 tiles

__global__ __launch_bounds__(512, 1) void encoder_mma(const float* __restrict__ be)
{
    extern __shared__ __align__(16) uint8_t smem[];
    const uint32_t sbase = smem_u32(smem);

    const int tid = threadIdx.x;
    const int warp = tid >> 5, lane = tid & 31;
    const int wm = warp & 3, wn = warp >> 2;          // 4 x 4 warp grid
    const int g = lane >> 2, tg = lane & 3;
    const int i4 = lane >> 3, r8 = lane & 7;
    const int m0 = blockIdx.x * ENC_BM;               // M fast -> B reuse in L2
    const int n0 = blockIdx.y * ENC_BN;

    float c[2][8][4];
    #pragma unroll
    for (int mi = 0; mi < 2; ++mi)
        #pragma unroll
        for (int nj = 0; nj < 8; ++nj)
            #pragma unroll
            for (int q = 0; q < 4; ++q) c[mi][nj][q] = 0.f;

    const int crow = tid >> 2, cc4 = tid & 3;

    auto issue = [&](int kt) {
        const uint32_t st = sbase + (kt % 3) * STG;
        const int k0 = kt * ENC_BK;
        const uint32_t ro = (uint32_t)(crow * 80 + cc4 * 16);
        const size_t ga = (size_t)(m0 + crow) * D_IN + k0 + cc4 * 8;
        cp16(st + ro, g_Xh + ga);
        cp16(st + A_ARR + ro, g_Xl + ga);
        const uint32_t bo = st + 2 * A_ARR;
        const size_t gb0 = (size_t)(n0 + crow) * D_IN + k0 + cc4 * 8;
        const size_t gb1 = (size_t)(n0 + 128 + crow) * D_IN + k0 + cc4 * 8;
        cp16(bo + ro, g_Wh + gb0);
        cp16(bo + (uint32_t)(128 * 80) + ro, g_Wh + gb1);
        cp16(bo + B_ARR + ro, g_Wl + gb0);
        cp16(bo + B_ARR + (uint32_t)(128 * 80) + ro, g_Wl + gb1);
        asm volatile("cp.async.commit_group;" ::: "memory");
    };

    issue(0);
    issue(1);

    for (int kt = 0; kt < NTT; ++kt) {
        if (kt < NTT - 1)
            asm volatile("cp.async.wait_group 1;" ::: "memory");
        else
            asm volatile("cp.async.wait_group 0;" ::: "memory");
        __syncthreads();
        if (kt + 2 < NTT) issue(kt + 2);

        const uint32_t st = sbase + (kt % 3) * STG;
        #pragma unroll
        for (int kc = 0; kc < 2; ++kc) {
            uint32_t a1f[2][4], a2f[2][4];
            #pragma unroll
            for (int mi = 0; mi < 2; ++mi) {
                int am = wm * 32 + mi * 16 + (i4 & 1) * 8 + r8;
                uint32_t off = st + (uint32_t)(am * 80 + kc * 32 + (i4 >> 1) * 16);
                ldsm_x4(a1f[mi], off);
                ldsm_x4(a2f[mi], off + A_ARR);
            }
            #pragma unroll
            for (int nj2 = 0; nj2 < 4; ++nj2) {
                int bn = wn * 64 + (nj2 * 2 + (i4 >> 1)) * 8 + r8;
                uint32_t boff = st + 2 * A_ARR +
                                (uint32_t)(bn * 80 + kc * 32 + (i4 & 1) * 16);
                uint32_t t1[4], t2[4];
                ldsm_x4(t1, boff);
                ldsm_x4(t2, boff + B_ARR);
                #pragma unroll
                for (int mi = 0; mi < 2; ++mi) {
                    mma_bf16(c[mi][nj2 * 2],     a1f[mi][0], a1f[mi][1], a1f[mi][2], a1f[mi][3], t1[0], t1[1]);
                    mma_bf16(c[mi][nj2 * 2 + 1], a1f[mi][0], a1f[mi][1], a1f[mi][2], a1f[mi][3], t1[2], t1[3]);
                    mma_bf16(c[mi][nj2 * 2],     a1f[mi][0], a1f[mi][1], a1f[mi][2], a1f[mi][3], t2[0], t2[1]);
                    mma_bf16(c[mi][nj2 * 2 + 1], a1f[mi][0], a1f[mi][1], a1f[mi][2], a1f[mi][3], t2[2], t2[3]);
                    mma_bf16(c[mi][nj2 * 2],     a2f[mi][0], a2f[mi][1], a2f[mi][2], a2f[mi][3], t1[0], t1[1]);
                    mma_bf16(c[mi][nj2 * 2 + 1], a2f[mi][0], a2f[mi][1], a2f[mi][2], a2f[mi][3], t1[2], t1[3]);
                }
            }
        }
        __syncthreads();
    }

    // epilogue: add b_enc, write
    #pragma unroll
    for (int mi = 0; mi < 2; ++mi) {
        #pragma unroll
        for (int nj = 0; nj < 8; ++nj) {
            int row0 = m0 + wm * 32 + mi * 16 + g;
            int col = n0 + wn * 64 + nj * 8 + 2 * tg;
            float2 be2 = *(const float2*)(be + col);
            float2 o0 = make_float2(c[mi][nj][0] + be2.x, c[mi][nj][1] + be2.y);
            float2 o1 = make_float2(c[mi][nj][2] + be2.x, c[mi][nj][3] + be2.y);
            *(float2*)&g_pre[(size_t)row0 * D_HID + col] = o0;
            *(float2*)&g_pre[(size_t)(row0 + 8) * D_HID + col] = o1;
        }
    }
}

// ---------------- exact radix-select ----------------
__device__ void radix_select(const uint32_t* keys, const uint32_t* deadb, bool useMask,
                             uint32_t* hist, int K, uint32_t* outT, int* outNeed, int lane)
{
    uint32_t prefix = 0;
    int kk = K;
    #pragma unroll 1
    for (int level = 0; level < 4; ++level) {
        const int shift = 24 - 8 * level;
        for (int b = threadIdx.x; b < 256; b += blockDim.x) hist[b] = 0;
        __syncthreads();
        const uint32_t hmask = (level == 0) ? 0u : (0xFFFFFFFFu << (shift + 8));
        for (int j = threadIdx.x; j < D_HID; j += blockDim.x) {
            uint32_t k = keys[j];
            if (useMask && !((deadb[j >> 5] >> (j & 31)) & 1u)) k = 0u;
            const bool valid = ((k & hmask) == prefix);
            const int bin = (int)((k >> shift) & 255u);
            const int tag = valid ? bin : (256 + lane);
            const unsigned grp = __match_any_sync(0xFFFFFFFFu, tag);
            if (valid && lane == (__ffs(grp) - 1))
                atomicAdd(&hist[bin], (uint32_t)__popc(grp));
        }
        __syncthreads();
        if (threadIdx.x == 0) {
            int acc = 0, b = 255;
            for (; b > 0; --b) {
                int c = (int)hist[b];
                if (acc + c >= kk) break;
                acc += c;
            }
            hist[256] = (uint32_t)b;
            hist[257] = (uint32_t)(kk - acc);
        }
        __syncthreads();
        prefix |= (hist[256] << shift);
        kk = (int)hist[257];
        __syncthreads();
    }
    *outT = prefix;
    *outNeed = kk;
}

// ---------------- per-row: main shortlist (top-96 approx) + aux top-512 -------------
__global__ __launch_bounds__(256) void topk_kernel(float* __restrict__ z_out)
{
    extern __shared__ uint32_t sm[];
    uint32_t* keys  = sm;
    uint32_t* deadb = sm + 16384;
    uint32_t* hist  = sm + 16896;
    int*      eq    = (int*)(sm + 17160);
    int*      ctr   = (int*)(sm + 17224);

    const int tid = threadIdx.x;
    const int lane = tid & 31;
    const int r = blockIdx.x;
    const size_t base = (size_t)r * D_HID;

    for (int j = tid; j < D_HID; j += 256) keys[j] = f2key(g_pre[base + j]);
    for (int w = tid; w < D_HID / 32; w += 256) deadb[w] = g_deadbits[w];
    __syncthreads();

    uint32_t T; int needEq;
    radix_select(keys, deadb, false, hist, 96, &T, &needEq, lane);
    if (tid == 0) ctr[0] = 0;
    __syncthreads();
    for (int j = tid; j < D_HID; j += 256) {
        z_out[base + j] = 0.f;
        if (keys[j] >= T) {
            int p = atomicAdd(&ctr[0], 1);
            if (p < NCAND) g_cand[(size_t)r * NCAND + p] = j;
        }
    }
    __syncthreads();
    if (tid == 0) g_cand_n[r] = min(ctr[0], NCAND);
    __syncthreads();

    uint32_t Ta; int needEqA;
    radix_select(keys, deadb, true, hist, KAUX, &Ta, &needEqA, lane);
    if (tid == 0) { ctr[0] = 0; ctr[1] = 0; }
    __syncthreads();
    for (int j = tid; j < D_HID; j += 256) {
        uint32_t k = ((deadb[j >> 5] >> (j & 31)) & 1u) ? keys[j] : 0u;
        if (k != 0u && k == Ta) { int p = atomicAdd(&ctr[1], 1); if (p < 64) eq[p] = j; }
    }
    __syncthreads();
    if (tid == 0) {
        int m = min(ctr[1], 64);
        int take = min(needEqA, m);
        for (int a = 0; a < take; ++a) {
            int best = a;
            for (int b = a + 1; b < m; ++b) if (eq[b] < eq[best]) best = b;
            int t2 = eq[a]; eq[a] = eq[best]; eq[best] = t2;
        }
        ctr[1] = take;
    }
    __syncthreads();
    const int nEqA = ctr[1];
    for (int j = tid; j < D_HID; j += 256) {
        uint32_t k = ((deadb[j >> 5] >> (j & 31)) & 1u) ? keys[j] : 0u;
        bool sel = (k > Ta);
        if (!sel && k != 0u && k == Ta)
            for (int a = 0; a < nEqA; ++a) if (eq[a] == j) { sel = true; break; }
        if (sel) {
            int p = atomicAdd(&ctr[0], 1);
            if (p < KAUX) { g_aux_idx[(size_t)r * KAUX + p] = j; g_aux_val[(size_t)r * KAUX + p] = key2f(keys[j]); }
        }
    }
    __syncthreads();
    if (tid == 0)
        for (int p = min(ctr[0], KAUX); p < KAUX; ++p) {
            g_aux_idx[(size_t)r * KAUX + p] = 0; g_aux_val[(size_t)r * KAUX + p] = -1.f;
        }
}

// ---------------- exact-Eigen refine (kc=248 panel folds, bitwise-ref values) -------
__global__ __launch_bounds__(128) void refine_kernel(
    const float* __restrict__ X, const float* __restrict__ WE,
    const float* __restrict__ be, const float* __restrict__ bd,
    float* __restrict__ z_out)
{
    __shared__ __align__(16) float xs[D_IN];
    __shared__ float vals[NCAND];
    __shared__ int   idxs[NCAND];
    __shared__ int   l0c;
    const int tid = threadIdx.x, r = blockIdx.x;
    if (tid == 0) l0c = 0;
    for (int k = tid; k < D_IN; k += 128)
        xs[k] = X[(size_t)r * D_IN + k] - bd[k];
    const int n = g_cand_n[r];
    if (tid < n) idxs[tid] = g_cand[(size_t)r * NCAND + tid];
    __syncthreads();

    if (tid < n) {
        const int fi = idxs[tid];
        const float4* w4 = (const float4*)(WE + (size_t)fi * D_IN);
        float acc = 0.f, pan = 0.f;
        int next = 248;
        for (int k = 0; k < D_IN; k += 4) {
            if (k == next) { acc += pan; pan = 0.f; next += 248; }
            float4 w = w4[k >> 2];
            pan = fmaf(xs[k + 0], w.x, pan);
            pan = fmaf(xs[k + 1], w.y, pan);
            pan = fmaf(xs[k + 2], w.z, pan);
            pan = fmaf(xs[k + 3], w.w, pan);
        }
        acc += pan;
        vals[tid] = acc + be[fi];
    }
    __syncthreads();

    if (tid < n) {
        const float v = vals[tid];
        const int myi = idxs[tid];
        int rank = 0;
        for (int j = 0; j < n; ++j) {
            const float u = vals[j];
            if (u > v || (u == v && idxs[j] < myi)) ++rank;
        }
        if (rank < KSEL) {
            g_sel_idx[r * KSEL + rank] = myi;
            g_sel_val[r * KSEL + rank] = v;
            z_out[(size_t)r * D_HID + myi] = fmaxf(v, 0.f);
            if (v > 0.f) atomicAdd(&l0c, 1);
        }
    }
    __syncthreads();
    if (tid == 0) g_l0_p[r] = (float)l0c;
}

// ---------------- sparse decode main (fp32 weights) ----------------
__global__ __launch_bounds__(256) void decode_main(const float* __restrict__ X,
                                                   float* __restrict__ xhat,
                                                   const float* __restrict__ bd)
{
    __shared__ int s_idx[KSEL];
    __shared__ float s_val[KSEL];
    __shared__ float red[8];
    const int tid = threadIdx.x, r = blockIdx.x;
    if (tid < KSEL) {
        s_idx[tid] = g_sel_idx[r * KSEL + tid];
        s_val[tid] = fmaxf(g_sel_val[r * KSEL + tid], 0.f);
    }
    __syncthreads();
    const float4* bd4 = (const float4*)bd;
    float4 acc0 = bd4[tid], acc1 = bd4[tid + 256];
    #pragma unroll 4
    for (int s = 0; s < KSEL; ++s) {
        float v = s_val[s];
        const float4* w = (const float4*)(g_WT + (size_t)s_idx[s] * D_IN);
        float4 w0 = w[tid], w1 = w[tid + 256];
        acc0.x += v * w0.x; acc0.y += v * w0.y; acc0.z += v * w0.z; acc0.w += v * w0.w;
        acc1.x += v * w1.x; acc1.y += v * w1.y; acc1.z += v * w1.z; acc1.w += v * w1.w;
    }
    const size_t b4 = (size_t)r * (D_IN / 4);
    ((float4*)xhat)[b4 + tid] = acc0;
    ((float4*)xhat)[b4 + tid + 256] = acc1;
    const float4* X4 = (const float4*)X;
    float4 x0 = X4[b4 + tid], x1 = X4[b4 + tid + 256];
    float d, loc = 0.f;
    d = acc0.x - x0.x; loc += d * d;  d = acc0.y - x0.y; loc += d * d;
    d = acc0.z - x0.z; loc += d * d;  d = acc0.w - x0.w; loc += d * d;
    d = acc1.x - x1.x; loc += d * d;  d = acc1.y - x1.y; loc += d * d;
    d = acc1.z - x1.z; loc += d * d;  d = acc1.w - x1.w; loc += d * d;
    #pragma unroll
    for (int o = 16; o; o >>= 1) loc += __shfl_down_sync(0xFFFFFFFFu, loc, o);
    if ((tid & 31) == 0) red[tid >> 5] = loc;
    __syncthreads();
    if (tid == 0) {
        float s = 0.f;
        for (int w2 = 0; w2 < 8; ++w2) s += red[w2];
        g_recon_p[r] = s;
    }
}

// ---------------- aux decode (bf16 weights) ----------------
__global__ __launch_bounds__(256) void decode_aux(const float* __restrict__ X,
                                                  const float* __restrict__ xhat)
{
    __shared__ int s_idx[KAUX];
    __shared__ float s_val[KAUX];
    __shared__ float red[8];
    const int tid = threadIdx.x, r = blockIdx.x;
    for (int s = tid; s < KAUX; s += 256) {
        s_idx[s] = g_aux_idx[(size_t)r * KAUX + s];
        s_val[s] = fmaxf(g_aux_val[(size_t)r * KAUX + s], 0.f);
    }
    __syncthreads();
    float acc[8];
    #pragma unroll
    for (int e = 0; e < 8; ++e) acc[e] = 0.f;
    #pragma unroll 2
    for (int s = 0; s < KAUX; ++s) {
        float v = s_val[s];
        uint4 w = *((const uint4*)(g_WTh + (size_t)s_idx[s] * (D_IN / 2)) + tid);
        float2 f0 = __bfloat1622float2(*reinterpret_cast<__nv_bfloat162*>(&w.x));
        float2 f1 = __bfloat1622float2(*reinterpret_cast<__nv_bfloat162*>(&w.y));
        float2 f2 = __bfloat1622float2(*reinterpret_cast<__nv_bfloat162*>(&w.z));
        float2 f3 = __bfloat1622float2(*reinterpret_cast<__nv_bfloat162*>(&w.w));
        acc[0] = fmaf(v, f0.x, acc[0]); acc[1] = fmaf(v, f0.y, acc[1]);
        acc[2] = fmaf(v, f1.x, acc[2]); acc[3] = fmaf(v, f1.y, acc[3]);
        acc[4] = fmaf(v, f2.x, acc[4]); acc[5] = fmaf(v, f2.y, acc[5]);
        acc[6] = fmaf(v, f3.x, acc[6]); acc[7] = fmaf(v, f3.y, acc[7]);
    }
    const size_t b4 = (size_t)r * (D_IN / 4) + tid * 2;
    const float4* X4 = (const float4*)X;
    const float4* H4 = (const float4*)xhat;
    float4 x0 = X4[b4], x1 = X4[b4 + 1];
    float4 h0 = H4[b4], h1 = H4[b4 + 1];
    float d, loc = 0.f;
    d = acc[0] - (x0.x - h0.x); loc += d * d;  d = acc[1] - (x0.y - h0.y); loc += d * d;
    d = acc[2] - (x0.z - h0.z); loc += d * d;  d = acc[3] - (x0.w - h0.w); loc += d * d;
    d = acc[4] - (x1.x - h1.x); loc += d * d;  d = acc[5] - (x1.y - h1.y); loc += d * d;
    d = acc[6] - (x1.z - h1.z); loc += d * d;  d = acc[7] - (x1.w - h1.w); loc += d * d;
    #pragma unroll
    for (int o = 16; o; o >>= 1) loc += __shfl_down_sync(0xFFFFFFFFu, loc, o);
    if ((tid & 31) == 0) red[tid >> 5] = loc;
    __syncthreads();
    if (tid == 0) {
        float s = 0.f;
        for (int w2 = 0; w2 < 8; ++w2) s += red[w2];
        g_aux_p[r] = s;
    }
}

// ---------------- final scalar reduction ----------------
__global__ void finalize_kernel(float* __restrict__ outs)
{
    __shared__ double sd[256];
    const int tid = threadIdx.x;
    double s = 0.0;
    for (int i = tid; i < BATCH; i += 256) s += (double)g_recon_p[i];
    sd[tid] = s; __syncthreads();
    for (int o = 128; o > 0; o >>= 1) { if (tid < o) sd[tid] += sd[tid + o]; __syncthreads(); }
    double recon = sd[0] / ((double)BATCH * (double)D_IN);
    __syncthreads();

    s = 0.0;
    for (int i = tid; i < BATCH; i += 256) s += (double)g_aux_p[i];
    sd[tid] = s; __syncthreads();
    for (int o = 128; o > 0; o >>= 1) { if (tid < o) sd[tid] += sd[tid + o]; __syncthreads(); }
    double aux = sd[0] / ((double)BATCH * (double)D_IN);
    __syncthreads();

    s = 0.0;
    for (int i = tid; i < BATCH; i += 256) s += (double)g_l0_p[i];
    sd[tid] = s; __syncthreads();
    for (int o = 128; o > 0; o >>= 1) { if (tid < o) sd[tid] += sd[tid + o]; __syncthreads(); }
    double l0 = sd[0] / (double)BATCH;

    if (tid == 0) {
        outs[0] = (float)(recon + aux * (1.0 / 32.0));
        outs[1] = (float)recon;
        outs[2] = (float)aux;
        outs[3] = (float)l0;
    }
}

// ---------------- launch ----------------
extern "C" void kernel_launch(void* const* d_in, const int* in_sizes, int n_in,
                              void* d_out, int out_size) {
    (void)in_sizes; (void)n_in; (void)out_size;
    const float* X  = (const float*)d_in[0];
    const float* WE = (const float*)d_in[1];
    const float* be = (const float*)d_in[2];
    const float* WD = (const float*)d_in[3];
    const float* bd = (const float*)d_in[4];
    const uint8_t* dm = (const uint8_t*)d_in[5];

    float* out = (float*)d_out;
    float* xhat = out;
    float* z = out + (size_t)BATCH * D_IN;
    float* scalars = z + (size_t)BATCH * D_HID;

    cudaFuncSetAttribute(topk_kernel, cudaFuncAttributeMaxDynamicSharedMemorySize, 70 * 1024);
    cudaFuncSetAttribute(encoder_mma, cudaFuncAttributeMaxDynamicSharedMemorySize, 3 * STG);

    prep_mask<<<1, 512>>>(dm);
    transpose_wdec<<<dim3(D_HID / 32, D_IN / 32), dim3(32, 8)>>>(WD);
    convert_wdec_bf16<<<(unsigned)(((size_t)D_HID * D_IN / 2 + 255) / 256), 256>>>();
    split_x<<<(unsigned)(((size_t)BATCH * D_IN / 4 + 255) / 256), 256>>>(X, bd);
    split_w<<<(unsigned)(((size_t)D_HID * D_IN / 4 + 255) / 256), 256>>>(WE);
    encoder_mma<<<dim3(BATCH / ENC_BM, D_HID / ENC_BN), 512, 3 * STG>>>(be);
    topk_kernel<<<BATCH, 256, 70 * 1024>>>(z);
    refine_kernel<<<BATCH, 128>>>(X, WE, be, bd, z);
    decode_main<<<BATCH, 256>>>(X, xhat, bd);
    decode_aux<<<BATCH, 256>>>(X, xhat);
    finalize_kernel<<<1, 256>>>(scalars);
}

// round 14
// speedup vs baseline: 1.1281x; 1.1281x over previous
#include <cuda_runtime.h>
#include <cuda_bf16.h>
#include <cstdint>
#include <math.h>

#define BATCH   8192
#define D_IN    2048
#define D_HID   16384
#define KSEL    64
#define KAUX    512
#define NCAND   128

// ---------------- scratch ----------------
__device__ float          g_pre[(size_t)BATCH * D_HID];
__device__ float          g_WT[(size_t)D_HID * D_IN];        // fp32 W_dec^T (decode_main)
__device__ uint32_t       g_WTh[(size_t)D_HID * D_IN / 2];   // bf16x2 W_dec^T (decode_aux)
__device__ __nv_bfloat16  g_Xh[(size_t)BATCH * D_IN];        // bf16 hi of (x - b_dec)
__device__ __nv_bfloat16  g_Wh[(size_t)D_HID * D_IN];        // bf16 hi of W_enc
__device__ __nv_bfloat16  g_Wl[(size_t)D_HID * D_IN];        // bf16 lo of W_enc
__device__ int      g_cand[(size_t)BATCH * NCAND];
__device__ int      g_cand_n[BATCH];
__device__ int      g_sel_idx[BATCH * KSEL];
__device__ float    g_sel_val[BATCH * KSEL];
__device__ int      g_aux_idx[(size_t)BATCH * KAUX];
__device__ float    g_aux_val[(size_t)BATCH * KAUX];
__device__ float    g_recon_p[BATCH];
__device__ float    g_aux_p[BATCH];
__device__ float    g_l0_p[BATCH];
__device__ unsigned g_deadbits[D_HID / 32];

// ---------------- helpers ----------------
__device__ __forceinline__ uint32_t f2key(float f) {
    uint32_t u = __float_as_uint(f);
    return (u & 0x80000000u) ? ~u : (u | 0x80000000u);
}
__device__ __forceinline__ float key2f(uint32_t k) {
    uint32_t u = (k & 0x80000000u) ? (k ^ 0x80000000u) : ~k;
    return __uint_as_float(u);
}
__device__ __forceinline__ void mma_bf16(float c[4], uint32_t a0, uint32_t a1,
                                         uint32_t a2, uint32_t a3,
                                         uint32_t b0, uint32_t b1) {
    asm volatile(
        "mma.sync.aligned.m16n8k16.row.col.f32.bf16.bf16.f32 "
        "{%0,%1,%2,%3}, {%4,%5,%6,%7}, {%8,%9}, {%0,%1,%2,%3};\n"
        : "+f"(c[0]), "+f"(c[1]), "+f"(c[2]), "+f"(c[3])
        : "r"(a0), "r"(a1), "r"(a2), "r"(a3), "r"(b0), "r"(b1));
}
__device__ __forceinline__ void ldsm_x4(uint32_t r[4], uint32_t saddr) {
    asm volatile("ldmatrix.sync.aligned.m8n8.x4.shared.b16 {%0,%1,%2,%3}, [%4];"
        : "=r"(r[0]), "=r"(r[1]), "=r"(r[2]), "=r"(r[3]) : "r"(saddr));
}
__device__ __forceinline__ void cp16(uint32_t dst, const void* src) {
    asm volatile("cp.async.cg.shared.global [%0], [%1], 16;" :: "r"(dst), "l"(src));
}
__device__ __forceinline__ uint32_t smem_u32(const void* p) {
    return (uint32_t)__cvta_generic_to_shared(p);
}

// ---------------- dead_mask prep ----------------
__global__ void prep_mask(const uint8_t* __restrict__ m) {
    __shared__ int viol;
    if (threadIdx.x == 0) viol = 0;
    __syncthreads();
    for (int i = threadIdx.x; i < D_HID; i += blockDim.x)
        if ((i & 3) && m[i]) viol = 1;
    __syncthreads();
    const bool is_i32 = (viol == 0);
    const int* mi = (const int*)m;
    for (int w = threadIdx.x; w < D_HID / 32; w += blockDim.x) {
        uint32_t bits = 0;
        #pragma unroll 4
        for (int b = 0; b < 32; ++b) {
            int j = w * 32 + b;
            bool d = is_i32 ? (mi[j] != 0) : (m[j] != 0);
            bits |= ((uint32_t)d) << b;
        }
        g_deadbits[w] = bits;
    }
}

// ---------------- W_dec transpose (fp32) ----------------
__global__ void transpose_wdec(const float* __restrict__ W) {
    __shared__ float t[32][33];
    int x = blockIdx.x * 32 + threadIdx.x;
    int y0 = blockIdx.y * 32;
    #pragma unroll
    for (int i = threadIdx.y; i < 32; i += 8)
        t[i][threadIdx.x] = W[(size_t)(y0 + i) * D_HID + x];
    __syncthreads();
    int xo = y0 + threadIdx.x;
    int yo0 = blockIdx.x * 32;
    #pragma unroll
    for (int i = threadIdx.y; i < 32; i += 8)
        g_WT[(size_t)(yo0 + i) * D_IN + xo] = t[threadIdx.x][i];
}

// ---------------- bf16 conversion of W_dec^T (aux decode) ----------------
__global__ void convert_wdec_bf16() {
    size_t i = (size_t)blockIdx.x * blockDim.x + threadIdx.x;
    if (i < (size_t)D_HID * D_IN / 2) {
        float2 f = *(const float2*)(g_WT + 2 * i);
        __nv_bfloat162 b = __floats2bfloat162_rn(f.x, f.y);
        g_WTh[i] = *reinterpret_cast<uint32_t*>(&b);
    }
}

// ---------------- precompute bf16 splits ----------------
__global__ void split_x(const float* __restrict__ X, const float* __restrict__ bd) {
    size_t i = ((size_t)blockIdx.x * blockDim.x + threadIdx.x) * 4;
    if (i < (size_t)BATCH * D_IN) {
        float4 xv = *(const float4*)(X + i);
        float4 dv = *(const float4*)(bd + (i & (D_IN - 1)));
        float v[4] = {xv.x - dv.x, xv.y - dv.y, xv.z - dv.z, xv.w - dv.w};
        __nv_bfloat16 h[4];
        #pragma unroll
        for (int e = 0; e < 4; ++e) h[e] = __float2bfloat16_rn(v[e]);
        *(uint2*)(g_Xh + i) = *(uint2*)h;
    }
}
__global__ void split_w(const float* __restrict__ WE) {
    size_t i = ((size_t)blockIdx.x * blockDim.x + threadIdx.x) * 4;
    if (i < (size_t)D_HID * D_IN) {
        float4 wv = *(const float4*)(WE + i);
        float v[4] = {wv.x, wv.y, wv.z, wv.w};
        __nv_bfloat16 h[4], l[4];
        #pragma unroll
        for (int e = 0; e < 4; ++e) {
            h[e] = __float2bfloat16_rn(v[e]);
            l[e] = __float2bfloat16_rn(v[e] - __bfloat162float(h[e]));
        }
        *(uint2*)(g_Wh + i) = *(uint2*)h;
        *(uint2*)(g_Wl + i) = *(uint2*)l;
    }
}

// ---------------- approx encoder: 2-product bf16 split (Ah*Bh + Ah*Bl) -------------
// CTA 128x128, 256 threads (2Mx4N warps), BK=32, 2-stage cp.async ring,
// 2 CTAs/SM. Row stride 80B -> conflict-free ldmatrix. Abs err ~7e-4 (used for
// shortlist + aux only; exact-Eigen refine supplies bitwise main selection).
#define ENC_BM 128
#define ENC_BN 128
#define ENC_BK 32
#define TILEB  (128 * 80)          // 10240 B per array
#define STAGEB (3 * TILEB)         // Xh, Wh, Wl = 30720 B
#define NT     (D_IN / ENC_BK)     // 64 k-tiles

__global__ __launch_bounds__(256, 2) void encoder_mma(const float* __restrict__ be)
{
    extern __shared__ __align__(16) uint32_t smem[];
    const uint32_t sbase = (uint32_t)__cvta_generic_to_shared(smem);

    const int tid = threadIdx.x;
    const int warp = tid >> 5, lane = tid & 31;
    const int wm = warp & 1, wn = warp >> 1;
    const int g = lane >> 2, tg = lane & 3;
    const int i4 = lane >> 3, r8 = lane & 7;
    const int m0 = blockIdx.x * ENC_BM;     // M fast -> B reuse in L2
    const int n0 = blockIdx.y * ENC_BN;

    float c[4][4][4];
    #pragma unroll
    for (int mi = 0; mi < 4; ++mi)
        #pragma unroll
        for (int nj = 0; nj < 4; ++nj)
            #pragma unroll
            for (int q = 0; q < 4; ++q) c[mi][nj][q] = 0.f;

    const int row0 = tid >> 2, c0 = (tid & 3);
    const int row1 = (tid + 256) >> 2, c1 = ((tid + 256) & 3);

    auto issue = [&](int kt) {
        const int k0 = kt * ENC_BK;
        const uint32_t sb = sbase + (kt & 1) * STAGEB;
        {
            uint32_t ro = (uint32_t)(row0 * 80 + c0 * 16);
            const size_t ga = (size_t)(m0 + row0) * D_IN + k0 + c0 * 8;
            const size_t gb = (size_t)(n0 + row0) * D_IN + k0 + c0 * 8;
            cp16(sb + ro, g_Xh + ga);
            cp16(sb + TILEB + ro, g_Wh + gb);
            cp16(sb + 2 * TILEB + ro, g_Wl + gb);
        }
        {
            uint32_t ro = (uint32_t)(row1 * 80 + c1 * 16);
            const size_t ga = (size_t)(m0 + row1) * D_IN + k0 + c1 * 8;
            const size_t gb = (size_t)(n0 + row1) * D_IN + k0 + c1 * 8;
            cp16(sb + ro, g_Xh + ga);
            cp16(sb + TILEB + ro, g_Wh + gb);
            cp16(sb + 2 * TILEB + ro, g_Wl + gb);
        }
        asm volatile("cp.async.commit_group;" ::: "memory");
    };

    issue(0);
    for (int kt = 0; kt < NT; ++kt) {
        if (kt + 1 < NT) {
            issue(kt + 1);
            asm volatile("cp.async.wait_group 1;" ::: "memory");
        } else {
            asm volatile("cp.async.wait_group 0;" ::: "memory");
        }
        __syncthreads();

        const uint32_t sb = sbase + (kt & 1) * STAGEB;
        #pragma unroll
        for (int kc = 0; kc < 2; ++kc) {
            uint32_t a1f[4][4], b1f[4][2], b2f[4][2];
            #pragma unroll
            for (int mi = 0; mi < 4; ++mi) {
                int am = wm * 64 + mi * 16 + (i4 & 1) * 8 + r8;
                uint32_t off = sb + (uint32_t)(am * 80 + kc * 32 + (i4 >> 1) * 16);
                ldsm_x4(a1f[mi], off);
            }
            #pragma unroll
            for (int nj2 = 0; nj2 < 2; ++nj2) {
                int bn = wn * 32 + (nj2 * 2 + (i4 >> 1)) * 8 + r8;
                uint32_t boff = sb + TILEB +
                                (uint32_t)(bn * 80 + kc * 32 + (i4 & 1) * 16);
                uint32_t t1[4], t2[4];
                ldsm_x4(t1, boff);
                ldsm_x4(t2, boff + TILEB);
                b1f[nj2 * 2][0] = t1[0]; b1f[nj2 * 2][1] = t1[1];
                b1f[nj2 * 2 + 1][0] = t1[2]; b1f[nj2 * 2 + 1][1] = t1[3];
                b2f[nj2 * 2][0] = t2[0]; b2f[nj2 * 2][1] = t2[1];
                b2f[nj2 * 2 + 1][0] = t2[2]; b2f[nj2 * 2 + 1][1] = t2[3];
            }
            #pragma unroll
            for (int nj = 0; nj < 4; ++nj)
                #pragma unroll
                for (int mi = 0; mi < 4; ++mi) {
                    mma_bf16(c[mi][nj], a1f[mi][0], a1f[mi][1], a1f[mi][2], a1f[mi][3],
                             b1f[nj][0], b1f[nj][1]);
                    mma_bf16(c[mi][nj], a1f[mi][0], a1f[mi][1], a1f[mi][2], a1f[mi][3],
                             b2f[nj][0], b2f[nj][1]);
                }
        }
        __syncthreads();
    }

    // epilogue: add b_enc, write
    #pragma unroll
    for (int mi = 0; mi < 4; ++mi) {
        #pragma unroll
        for (int nj = 0; nj < 4; ++nj) {
            int rrow = m0 + wm * 64 + mi * 16 + g;
            int col = n0 + wn * 32 + nj * 8 + 2 * tg;
            float2 be2 = *(const float2*)(be + col);
            float2 o0 = make_float2(c[mi][nj][0] + be2.x, c[mi][nj][1] + be2.y);
            float2 o1 = make_float2(c[mi][nj][2] + be2.x, c[mi][nj][3] + be2.y);
            *(float2*)&g_pre[(size_t)rrow * D_HID + col] = o0;
            *(float2*)&g_pre[(size_t)(rrow + 8) * D_HID + col] = o1;
        }
    }
}

// ---------------- exact radix-select ----------------
__device__ void radix_select(const uint32_t* keys, const uint32_t* deadb, bool useMask,
                             uint32_t* hist, int K, uint32_t* outT, int* outNeed, int lane)
{
    uint32_t prefix = 0;
    int kk = K;
    #pragma unroll 1
    for (int level = 0; level < 4; ++level) {
        const int shift = 24 - 8 * level;
        for (int b = threadIdx.x; b < 256; b += blockDim.x) hist[b] = 0;
        __syncthreads();
        const uint32_t hmask = (level == 0) ? 0u : (0xFFFFFFFFu << (shift + 8));
        for (int j = threadIdx.x; j < D_HID; j += blockDim.x) {
            uint32_t k = keys[j];
            if (useMask && !((deadb[j >> 5] >> (j & 31)) & 1u)) k = 0u;
            const bool valid = ((k & hmask) == prefix);
            const int bin = (int)((k >> shift) & 255u);
            const int tag = valid ? bin : (256 + lane);
            const unsigned grp = __match_any_sync(0xFFFFFFFFu, tag);
            if (valid && lane == (__ffs(grp) - 1))
                atomicAdd(&hist[bin], (uint32_t)__popc(grp));
        }
        __syncthreads();
        if (threadIdx.x == 0) {
            int acc = 0, b = 255;
            for (; b > 0; --b) {
                int c = (int)hist[b];
                if (acc + c >= kk) break;
                acc += c;
            }
            hist[256] = (uint32_t)b;
            hist[257] = (uint32_t)(kk - acc);
        }
        __syncthreads();
        prefix |= (hist[256] << shift);
        kk = (int)hist[257];
        __syncthreads();
    }
    *outT = prefix;
    *outNeed = kk;
}

// ---------------- per-row: main shortlist (top-96 approx) + aux top-512 -------------
__global__ __launch_bounds__(256) void topk_kernel(float* __restrict__ z_out)
{
    extern __shared__ uint32_t sm[];
    uint32_t* keys  = sm;
    uint32_t* deadb = sm + 16384;
    uint32_t* hist  = sm + 16896;
    int*      eq    = (int*)(sm + 17160);
    int*      ctr   = (int*)(sm + 17224);

    const int tid = threadIdx.x;
    const int lane = tid & 31;
    const int r = blockIdx.x;
    const size_t base = (size_t)r * D_HID;

    for (int j = tid; j < D_HID; j += 256) keys[j] = f2key(g_pre[base + j]);
    for (int w = tid; w < D_HID / 32; w += 256) deadb[w] = g_deadbits[w];
    __syncthreads();

    uint32_t T; int needEq;
    radix_select(keys, deadb, false, hist, 96, &T, &needEq, lane);
    if (tid == 0) ctr[0] = 0;
    __syncthreads();
    for (int j = tid; j < D_HID; j += 256) {
        z_out[base + j] = 0.f;
        if (keys[j] >= T) {
            int p = atomicAdd(&ctr[0], 1);
            if (p < NCAND) g_cand[(size_t)r * NCAND + p] = j;
        }
    }
    __syncthreads();
    if (tid == 0) g_cand_n[r] = min(ctr[0], NCAND);
    __syncthreads();

    uint32_t Ta; int needEqA;
    radix_select(keys, deadb, true, hist, KAUX, &Ta, &needEqA, lane);
    if (tid == 0) { ctr[0] = 0; ctr[1] = 0; }
    __syncthreads();
    for (int j = tid; j < D_HID; j += 256) {
        uint32_t k = ((deadb[j >> 5] >> (j & 31)) & 1u) ? keys[j] : 0u;
        if (k != 0u && k == Ta) { int p = atomicAdd(&ctr[1], 1); if (p < 64) eq[p] = j; }
    }
    __syncthreads();
    if (tid == 0) {
        int m = min(ctr[1], 64);
        int take = min(needEqA, m);
        for (int a = 0; a < take; ++a) {
            int best = a;
            for (int b = a + 1; b < m; ++b) if (eq[b] < eq[best]) best = b;
            int t2 = eq[a]; eq[a] = eq[best]; eq[best] = t2;
        }
        ctr[1] = take;
    }
    __syncthreads();
    const int nEqA = ctr[1];
    for (int j = tid; j < D_HID; j += 256) {
        uint32_t k = ((deadb[j >> 5] >> (j & 31)) & 1u) ? keys[j] : 0u;
        bool sel = (k > Ta);
        if (!sel && k != 0u && k == Ta)
            for (int a = 0; a < nEqA; ++a) if (eq[a] == j) { sel = true; break; }
        if (sel) {
            int p = atomicAdd(&ctr[0], 1);
            if (p < KAUX) { g_aux_idx[(size_t)r * KAUX + p] = j; g_aux_val[(size_t)r * KAUX + p] = key2f(keys[j]); }
        }
    }
    __syncthreads();
    if (tid == 0)
        for (int p = min(ctr[0], KAUX); p < KAUX; ++p) {
            g_aux_idx[(size_t)r * KAUX + p] = 0; g_aux_val[(size_t)r * KAUX + p] = -1.f;
        }
}

// ---------------- exact-Eigen refine (kc=248 panel folds, bitwise-ref values) -------
__global__ __launch_bounds__(128) void refine_kernel(
    const float* __restrict__ X, const float* __restrict__ WE,
    const float* __restrict__ be, const float* __restrict__ bd,
    float* __restrict__ z_out)
{
    __shared__ __align__(16) float xs[D_IN];
    __shared__ float vals[NCAND];
    __shared__ int   idxs[NCAND];
    __shared__ int   l0c;
    const int tid = threadIdx.x, r = blockIdx.x;
    if (tid == 0) l0c = 0;
    for (int k = tid; k < D_IN; k += 128)
        xs[k] = X[(size_t)r * D_IN + k] - bd[k];
    const int n = g_cand_n[r];
    if (tid < n) idxs[tid] = g_cand[(size_t)r * NCAND + tid];
    __syncthreads();

    if (tid < n) {
        const int fi = idxs[tid];
        const float4* w4 = (const float4*)(WE + (size_t)fi * D_IN);
        float acc = 0.f, pan = 0.f;
        int next = 248;
        for (int k = 0; k < D_IN; k += 4) {
            if (k == next) { acc += pan; pan = 0.f; next += 248; }
            float4 w = w4[k >> 2];
            pan = fmaf(xs[k + 0], w.x, pan);
            pan = fmaf(xs[k + 1], w.y, pan);
            pan = fmaf(xs[k + 2], w.z, pan);
            pan = fmaf(xs[k + 3], w.w, pan);
        }
        acc += pan;
        vals[tid] = acc + be[fi];
    }
    __syncthreads();

    if (tid < n) {
        const float v = vals[tid];
        const int myi = idxs[tid];
        int rank = 0;
        for (int j = 0; j < n; ++j) {
            const float u = vals[j];
            if (u > v || (u == v && idxs[j] < myi)) ++rank;
        }
        if (rank < KSEL) {
            g_sel_idx[r * KSEL + rank] = myi;
            g_sel_val[r * KSEL + rank] = v;
            z_out[(size_t)r * D_HID + myi] = fmaxf(v, 0.f);
            if (v > 0.f) atomicAdd(&l0c, 1);
        }
    }
    __syncthreads();
    if (tid == 0) g_l0_p[r] = (float)l0c;
}

// ---------------- sparse decode main (fp32 weights) ----------------
__global__ __launch_bounds__(256) void decode_main(const float* __restrict__ X,
                                                   float* __restrict__ xhat,
                                                   const float* __restrict__ bd)
{
    __shared__ int s_idx[KSEL];
    __shared__ float s_val[KSEL];
    __shared__ float red[8];
    const int tid = threadIdx.x, r = blockIdx.x;
    if (tid < KSEL) {
        s_idx[tid] = g_sel_idx[r * KSEL + tid];
        s_val[tid] = fmaxf(g_sel_val[r * KSEL + tid], 0.f);
    }
    __syncthreads();
    const float4* bd4 = (const float4*)bd;
    float4 acc0 = bd4[tid], acc1 = bd4[tid + 256];
    #pragma unroll 4
    for (int s = 0; s < KSEL; ++s) {
        float v = s_val[s];
        const float4* w = (const float4*)(g_WT + (size_t)s_idx[s] * D_IN);
        float4 w0 = w[tid], w1 = w[tid + 256];
        acc0.x += v * w0.x; acc0.y += v * w0.y; acc0.z += v * w0.z; acc0.w += v * w0.w;
        acc1.x += v * w1.x; acc1.y += v * w1.y; acc1.z += v * w1.z; acc1.w += v * w1.w;
    }
    const size_t b4 = (size_t)r * (D_IN / 4);
    ((float4*)xhat)[b4 + tid] = acc0;
    ((float4*)xhat)[b4 + tid + 256] = acc1;
    const float4* X4 = (const float4*)X;
    float4 x0 = X4[b4 + tid], x1 = X4[b4 + tid + 256];
    float d, loc = 0.f;
    d = acc0.x - x0.x; loc += d * d;  d = acc0.y - x0.y; loc += d * d;
    d = acc0.z - x0.z; loc += d * d;  d = acc0.w - x0.w; loc += d * d;
    d = acc1.x - x1.x; loc += d * d;  d = acc1.y - x1.y; loc += d * d;
    d = acc1.z - x1.z; loc += d * d;  d = acc1.w - x1.w; loc += d * d;
    #pragma unroll
    for (int o = 16; o; o >>= 1) loc += __shfl_down_sync(0xFFFFFFFFu, loc, o);
    if ((tid & 31) == 0) red[tid >> 5] = loc;
    __syncthreads();
    if (tid == 0) {
        float s = 0.f;
        for (int w2 = 0; w2 < 8; ++w2) s += red[w2];
        g_recon_p[r] = s;
    }
}

// ---------------- aux decode (bf16 weights) ----------------
__global__ __launch_bounds__(256) void decode_aux(const float* __restrict__ X,
                                                  const float* __restrict__ xhat)
{
    __shared__ int s_idx[KAUX];
    __shared__ float s_val[KAUX];
    __shared__ float red[8];
    const int tid = threadIdx.x, r = blockIdx.x;
    for (int s = tid; s < KAUX; s += 256) {
        s_idx[s] = g_aux_idx[(size_t)r * KAUX + s];
        s_val[s] = fmaxf(g_aux_val[(size_t)r * KAUX + s], 0.f);
    }
    __syncthreads();
    float acc[8];
    #pragma unroll
    for (int e = 0; e < 8; ++e) acc[e] = 0.f;
    #pragma unroll 2
    for (int s = 0; s < KAUX; ++s) {
        float v = s_val[s];
        uint4 w = *((const uint4*)(g_WTh + (size_t)s_idx[s] * (D_IN / 2)) + tid);
        float2 f0 = __bfloat1622float2(*reinterpret_cast<__nv_bfloat162*>(&w.x));
        float2 f1 = __bfloat1622float2(*reinterpret_cast<__nv_bfloat162*>(&w.y));
        float2 f2 = __bfloat1622float2(*reinterpret_cast<__nv_bfloat162*>(&w.z));
        float2 f3 = __bfloat1622float2(*reinterpret_cast<__nv_bfloat162*>(&w.w));
        acc[0] = fmaf(v, f0.x, acc[0]); acc[1] = fmaf(v, f0.y, acc[1]);
        acc[2] = fmaf(v, f1.x, acc[2]); acc[3] = fmaf(v, f1.y, acc[3]);
        acc[4] = fmaf(v, f2.x, acc[4]); acc[5] = fmaf(v, f2.y, acc[5]);
        acc[6] = fmaf(v, f3.x, acc[6]); acc[7] = fmaf(v, f3.y, acc[7]);
    }
    const size_t b4 = (size_t)r * (D_IN / 4) + tid * 2;
    const float4* X4 = (const float4*)X;
    const float4* H4 = (const float4*)xhat;
    float4 x0 = X4[b4], x1 = X4[b4 + 1];
    float4 h0 = H4[b4], h1 = H4[b4 + 1];
    float d, loc = 0.f;
    d = acc[0] - (x0.x - h0.x); loc += d * d;  d = acc[1] - (x0.y - h0.y); loc += d * d;
    d = acc[2] - (x0.z - h0.z); loc += d * d;  d = acc[3] - (x0.w - h0.w); loc += d * d;
    d = acc[4] - (x1.x - h1.x); loc += d * d;  d = acc[5] - (x1.y - h1.y); loc += d * d;
    d = acc[6] - (x1.z - h1.z); loc += d * d;  d = acc[7] - (x1.w - h1.w); loc += d * d;
    #pragma unroll
    for (int o = 16; o; o >>= 1) loc += __shfl_down_sync(0xFFFFFFFFu, loc, o);
    if ((tid & 31) == 0) red[tid >> 5] = loc;
    __syncthreads();
    if (tid == 0) {
        float s = 0.f;
        for (int w2 = 0; w2 < 8; ++w2) s += red[w2];
        g_aux_p[r] = s;
    }
}

// ---------------- final scalar reduction ----------------
__global__ void finalize_kernel(float* __restrict__ outs)
{
    __shared__ double sd[256];
    const int tid = threadIdx.x;
    double s = 0.0;
    for (int i = tid; i < BATCH; i += 256) s += (double)g_recon_p[i];
    sd[tid] = s; __syncthreads();
    for (int o = 128; o > 0; o >>= 1) { if (tid < o) sd[tid] += sd[tid + o]; __syncthreads(); }
    double recon = sd[0] / ((double)BATCH * (double)D_IN);
    __syncthreads();

    s = 0.0;
    for (int i = tid; i < BATCH; i += 256) s += (double)g_aux_p[i];
    sd[tid] = s; __syncthreads();
    for (int o = 128; o > 0; o >>= 1) { if (tid < o) sd[tid] += sd[tid + o]; __syncthreads(); }
    double aux = sd[0] / ((double)BATCH * (double)D_IN);
    __syncthreads();

    s = 0.0;
    for (int i = tid; i < BATCH; i += 256) s += (double)g_l0_p[i];
    sd[tid] = s; __syncthreads();
    for (int o = 128; o > 0; o >>= 1) { if (tid < o) sd[tid] += sd[tid + o]; __syncthreads(); }
    double l0 = sd[0] / (double)BATCH;

    if (tid == 0) {
        outs[0] = (float)(recon + aux * (1.0 / 32.0));
        outs[1] = (float)recon;
        outs[2] = (float)aux;
        outs[3] = (float)l0;
    }
}

// ---------------- launch ----------------
extern "C" void kernel_launch(void* const* d_in, const int* in_sizes, int n_in,
                              void* d_out, int out_size) {
    (void)in_sizes; (void)n_in; (void)out_size;
    const float* X  = (const float*)d_in[0];
    const float* WE = (const float*)d_in[1];
    const float* be = (const float*)d_in[2];
    const float* WD = (const float*)d_in[3];
    const float* bd = (const float*)d_in[4];
    const uint8_t* dm = (const uint8_t*)d_in[5];

    float* out = (float*)d_out;
    float* xhat = out;
    float* z = out + (size_t)BATCH * D_IN;
    float* scalars = z + (size_t)BATCH * D_HID;

    cudaFuncSetAttribute(topk_kernel, cudaFuncAttributeMaxDynamicSharedMemorySize, 70 * 1024);
    cudaFuncSetAttribute(encoder_mma, cudaFuncAttributeMaxDynamicSharedMemorySize, 2 * STAGEB);

    prep_mask<<<1, 512>>>(dm);
    transpose_wdec<<<dim3(D_HID / 32, D_IN / 32), dim3(32, 8)>>>(WD);
    convert_wdec_bf16<<<(unsigned)(((size_t)D_HID * D_IN / 2 + 255) / 256), 256>>>();
    split_x<<<(unsigned)(((size_t)BATCH * D_IN / 4 + 255) / 256), 256>>>(X, bd);
    split_w<<<(unsigned)(((size_t)D_HID * D_IN / 4 + 255) / 256), 256>>>(WE);
    encoder_mma<<<dim3(BATCH / ENC_BM, D_HID / ENC_BN), 256, 2 * STAGEB>>>(be);
    topk_kernel<<<BATCH, 256, 70 * 1024>>>(z);
    refine_kernel<<<BATCH, 128>>>(X, WE, be, bd, z);
    decode_main<<<BATCH, 256>>>(X, xhat, bd);
    decode_aux<<<BATCH, 256>>>(X, xhat);
    finalize_kernel<<<1, 256>>>(scalars);
}

// round 16
// speedup vs baseline: 1.2512x; 1.1092x over previous
#include <cuda_runtime.h>
#include <cuda_bf16.h>
#include <cstdint>
#include <math.h>

#define BATCH   8192
#define D_IN    2048
#define D_HID   16384
#define KSEL    64
#define KAUX    512
#define NCAND   128

// ---------------- scratch ----------------
__device__ float          g_pre[(size_t)BATCH * D_HID];
__device__ float          g_WT[(size_t)D_HID * D_IN];        // fp32 W_dec^T (decode_main)
__device__ uint32_t       g_WTh[(size_t)D_HID * D_IN / 2];   // bf16x2 W_dec^T (decode_aux)
__device__ __nv_bfloat16  g_Xh[(size_t)BATCH * D_IN];        // bf16 of (x - b_dec)
__device__ __nv_bfloat16  g_Wh[(size_t)D_HID * D_IN];        // bf16 of W_enc
__device__ int      g_cand[(size_t)BATCH * NCAND];
__device__ int      g_cand_n[BATCH];
__device__ int      g_sel_idx[BATCH * KSEL];
__device__ float    g_sel_val[BATCH * KSEL];
__device__ int      g_aux_idx[(size_t)BATCH * KAUX];
__device__ float    g_aux_val[(size_t)BATCH * KAUX];
__device__ float    g_recon_p[BATCH];
__device__ float    g_aux_p[BATCH];
__device__ float    g_l0_p[BATCH];
__device__ unsigned g_deadbits[D_HID / 32];

// ---------------- helpers ----------------
__device__ __forceinline__ uint32_t f2key(float f) {
    uint32_t u = __float_as_uint(f);
    return (u & 0x80000000u) ? ~u : (u | 0x80000000u);
}
__device__ __forceinline__ float key2f(uint32_t k) {
    uint32_t u = (k & 0x80000000u) ? (k ^ 0x80000000u) : ~k;
    return __uint_as_float(u);
}
__device__ __forceinline__ void mma_bf16(float c[4], uint32_t a0, uint32_t a1,
                                         uint32_t a2, uint32_t a3,
                                         uint32_t b0, uint32_t b1) {
    asm volatile(
        "mma.sync.aligned.m16n8k16.row.col.f32.bf16.bf16.f32 "
        "{%0,%1,%2,%3}, {%4,%5,%6,%7}, {%8,%9}, {%0,%1,%2,%3};\n"
        : "+f"(c[0]), "+f"(c[1]), "+f"(c[2]), "+f"(c[3])
        : "r"(a0), "r"(a1), "r"(a2), "r"(a3), "r"(b0), "r"(b1));
}
__device__ __forceinline__ void ldsm_x4(uint32_t r[4], uint32_t saddr) {
    asm volatile("ldmatrix.sync.aligned.m8n8.x4.shared.b16 {%0,%1,%2,%3}, [%4];"
        : "=r"(r[0]), "=r"(r[1]), "=r"(r[2]), "=r"(r[3]) : "r"(saddr));
}
__device__ __forceinline__ void cp16(uint32_t dst, const void* src) {
    asm volatile("cp.async.cg.shared.global [%0], [%1], 16;" :: "r"(dst), "l"(src));
}
__device__ __forceinline__ uint32_t smem_u32(const void* p) {
    return (uint32_t)__cvta_generic_to_shared(p);
}

// ---------------- dead_mask prep ----------------
__global__ void prep_mask(const uint8_t* __restrict__ m) {
    __shared__ int viol;
    if (threadIdx.x == 0) viol = 0;
    __syncthreads();
    for (int i = threadIdx.x; i < D_HID; i += blockDim.x)
        if ((i & 3) && m[i]) viol = 1;
    __syncthreads();
    const bool is_i32 = (viol == 0);
    const int* mi = (const int*)m;
    for (int w = threadIdx.x; w < D_HID / 32; w += blockDim.x) {
        uint32_t bits = 0;
        #pragma unroll 4
        for (int b = 0; b < 32; ++b) {
            int j = w * 32 + b;
            bool d = is_i32 ? (mi[j] != 0) : (m[j] != 0);
            bits |= ((uint32_t)d) << b;
        }
        g_deadbits[w] = bits;
    }
}

// ---------------- W_dec transpose (fp32) ----------------
__global__ void transpose_wdec(const float* __restrict__ W) {
    __shared__ float t[32][33];
    int x = blockIdx.x * 32 + threadIdx.x;
    int y0 = blockIdx.y * 32;
    #pragma unroll
    for (int i = threadIdx.y; i < 32; i += 8)
        t[i][threadIdx.x] = W[(size_t)(y0 + i) * D_HID + x];
    __syncthreads();
    int xo = y0 + threadIdx.x;
    int yo0 = blockIdx.x * 32;
    #pragma unroll
    for (int i = threadIdx.y; i < 32; i += 8)
        g_WT[(size_t)(yo0 + i) * D_IN + xo] = t[threadIdx.x][i];
}

// ---------------- bf16 conversion of W_dec^T (aux decode) ----------------
__global__ void convert_wdec_bf16() {
    size_t i = (size_t)blockIdx.x * blockDim.x + threadIdx.x;
    if (i < (size_t)D_HID * D_IN / 2) {
        float2 f = *(const float2*)(g_WT + 2 * i);
        __nv_bfloat162 b = __floats2bfloat162_rn(f.x, f.y);
        g_WTh[i] = *reinterpret_cast<uint32_t*>(&b);
    }
}

// ---------------- precompute bf16 operands ----------------
__global__ void split_x(const float* __restrict__ X, const float* __restrict__ bd) {
    size_t i = ((size_t)blockIdx.x * blockDim.x + threadIdx.x) * 4;
    if (i < (size_t)BATCH * D_IN) {
        float4 xv = *(const float4*)(X + i);
        float4 dv = *(const float4*)(bd + (i & (D_IN - 1)));
        float v[4] = {xv.x - dv.x, xv.y - dv.y, xv.z - dv.z, xv.w - dv.w};
        __nv_bfloat16 h[4];
        #pragma unroll
        for (int e = 0; e < 4; ++e) h[e] = __float2bfloat16_rn(v[e]);
        *(uint2*)(g_Xh + i) = *(uint2*)h;
    }
}
__global__ void split_w(const float* __restrict__ WE) {
    size_t i = ((size_t)blockIdx.x * blockDim.x + threadIdx.x) * 4;
    if (i < (size_t)D_HID * D_IN) {
        float4 wv = *(const float4*)(WE + i);
        __nv_bfloat16 h[4];
        h[0] = __float2bfloat16_rn(wv.x);
        h[1] = __float2bfloat16_rn(wv.y);
        h[2] = __float2bfloat16_rn(wv.z);
        h[3] = __float2bfloat16_rn(wv.w);
        *(uint2*)(g_Wh + i) = *(uint2*)h;
    }
}

// ---------------- approx encoder: single-product bf16 (Ah*Bh) ----------------------
// CTA 128x128, 256 threads (2Mx4N warps), BK=32, 2-stage cp.async ring,
// 2 CTAs/SM. Row stride 80B -> conflict-free ldmatrix. Abs err ~1.6e-3 (used for
// shortlist + aux only; exact-Eigen refine supplies bitwise main selection;
// aux boundary swaps are loss-neutral by the e_hat swap-cancellation identity).
#define ENC_BM 128
#define ENC_BN 128
#define ENC_BK 32
#define TILEB  (128 * 80)          // 10240 B per array
#define STAGEB (2 * TILEB)         // Xh, Wh = 20480 B
#define NT     (D_IN / ENC_BK)     // 64 k-tiles

__global__ __launch_bounds__(256, 2) void encoder_mma(const float* __restrict__ be)
{
    extern __shared__ __align__(16) uint32_t smem[];
    const uint32_t sbase = (uint32_t)__cvta_generic_to_shared(smem);

    const int tid = threadIdx.x;
    const int warp = tid >> 5, lane = tid & 31;
    const int wm = warp & 1, wn = warp >> 1;
    const int g = lane >> 2, tg = lane & 3;
    const int i4 = lane >> 3, r8 = lane & 7;
    const int m0 = blockIdx.x * ENC_BM;     // M fast -> W tiles stay L2-resident
    const int n0 = blockIdx.y * ENC_BN;

    float c[4][4][4];
    #pragma unroll
    for (int mi = 0; mi < 4; ++mi)
        #pragma unroll
        for (int nj = 0; nj < 4; ++nj)
            #pragma unroll
            for (int q = 0; q < 4; ++q) c[mi][nj][q] = 0.f;

    const int row0 = tid >> 2, c0 = (tid & 3);
    const int row1 = (tid + 256) >> 2, c1 = ((tid + 256) & 3);

    auto issue = [&](int kt) {
        const int k0 = kt * ENC_BK;
        const uint32_t sb = sbase + (kt & 1) * STAGEB;
        {
            uint32_t ro = (uint32_t)(row0 * 80 + c0 * 16);
            const size_t ga = (size_t)(m0 + row0) * D_IN + k0 + c0 * 8;
            const size_t gb = (size_t)(n0 + row0) * D_IN + k0 + c0 * 8;
            cp16(sb + ro, g_Xh + ga);
            cp16(sb + TILEB + ro, g_Wh + gb);
        }
        {
            uint32_t ro = (uint32_t)(row1 * 80 + c1 * 16);
            const size_t ga = (size_t)(m0 + row1) * D_IN + k0 + c1 * 8;
            const size_t gb = (size_t)(n0 + row1) * D_IN + k0 + c1 * 8;
            cp16(sb + ro, g_Xh + ga);
            cp16(sb + TILEB + ro, g_Wh + gb);
        }
        asm volatile("cp.async.commit_group;" ::: "memory");
    };

    issue(0);
    for (int kt = 0; kt < NT; ++kt) {
        if (kt + 1 < NT) {
            issue(kt + 1);
            asm volatile("cp.async.wait_group 1;" ::: "memory");
        } else {
            asm volatile("cp.async.wait_group 0;" ::: "memory");
        }
        __syncthreads();

        const uint32_t sb = sbase + (kt & 1) * STAGEB;
        #pragma unroll
        for (int kc = 0; kc < 2; ++kc) {
            uint32_t a1f[4][4], b1f[4][2];
            #pragma unroll
            for (int mi = 0; mi < 4; ++mi) {
                int am = wm * 64 + mi * 16 + (i4 & 1) * 8 + r8;
                uint32_t off = sb + (uint32_t)(am * 80 + kc * 32 + (i4 >> 1) * 16);
                ldsm_x4(a1f[mi], off);
            }
            #pragma unroll
            for (int nj2 = 0; nj2 < 2; ++nj2) {
                int bn = wn * 32 + (nj2 * 2 + (i4 >> 1)) * 8 + r8;
                uint32_t boff = sb + TILEB +
                                (uint32_t)(bn * 80 + kc * 32 + (i4 & 1) * 16);
                uint32_t t1[4];
                ldsm_x4(t1, boff);
                b1f[nj2 * 2][0] = t1[0]; b1f[nj2 * 2][1] = t1[1];
                b1f[nj2 * 2 + 1][0] = t1[2]; b1f[nj2 * 2 + 1][1] = t1[3];
            }
            #pragma unroll
            for (int nj = 0; nj < 4; ++nj)
                #pragma unroll
                for (int mi = 0; mi < 4; ++mi)
                    mma_bf16(c[mi][nj], a1f[mi][0], a1f[mi][1], a1f[mi][2], a1f[mi][3],
                             b1f[nj][0], b1f[nj][1]);
        }
        __syncthreads();
    }

    // epilogue: add b_enc, write
    #pragma unroll
    for (int mi = 0; mi < 4; ++mi) {
        #pragma unroll
        for (int nj = 0; nj < 4; ++nj) {
            int rrow = m0 + wm * 64 + mi * 16 + g;
            int col = n0 + wn * 32 + nj * 8 + 2 * tg;
            float2 be2 = *(const float2*)(be + col);
            float2 o0 = make_float2(c[mi][nj][0] + be2.x, c[mi][nj][1] + be2.y);
            float2 o1 = make_float2(c[mi][nj][2] + be2.x, c[mi][nj][3] + be2.y);
            *(float2*)&g_pre[(size_t)rrow * D_HID + col] = o0;
            *(float2*)&g_pre[(size_t)(rrow + 8) * D_HID + col] = o1;
        }
    }
}

// ---------------- exact radix-select ----------------
__device__ void radix_select(const uint32_t* keys, const uint32_t* deadb, bool useMask,
                             uint32_t* hist, int K, uint32_t* outT, int* outNeed, int lane)
{
    uint32_t prefix = 0;
    int kk = K;
    #pragma unroll 1
    for (int level = 0; level < 4; ++level) {
        const int shift = 24 - 8 * level;
        for (int b = threadIdx.x; b < 256; b += blockDim.x) hist[b] = 0;
        __syncthreads();
        const uint32_t hmask = (level == 0) ? 0u : (0xFFFFFFFFu << (shift + 8));
        for (int j = threadIdx.x; j < D_HID; j += blockDim.x) {
            uint32_t k = keys[j];
            if (useMask && !((deadb[j >> 5] >> (j & 31)) & 1u)) k = 0u;
            const bool valid = ((k & hmask) == prefix);
            const int bin = (int)((k >> shift) & 255u);
            const int tag = valid ? bin : (256 + lane);
            const unsigned grp = __match_any_sync(0xFFFFFFFFu, tag);
            if (valid && lane == (__ffs(grp) - 1))
                atomicAdd(&hist[bin], (uint32_t)__popc(grp));
        }
        __syncthreads();
        if (threadIdx.x == 0) {
            int acc = 0, b = 255;
            for (; b > 0; --b) {
                int c = (int)hist[b];
                if (acc + c >= kk) break;
                acc += c;
            }
            hist[256] = (uint32_t)b;
            hist[257] = (uint32_t)(kk - acc);
        }
        __syncthreads();
        prefix |= (hist[256] << shift);
        kk = (int)hist[257];
        __syncthreads();
    }
    *outT = prefix;
    *outNeed = kk;
}

// ---------------- per-row: main shortlist (top-96 approx) + aux top-512 -------------
__global__ __launch_bounds__(256) void topk_kernel(float* __restrict__ z_out)
{
    extern __shared__ uint32_t sm[];
    uint32_t* keys  = sm;
    uint32_t* deadb = sm + 16384;
    uint32_t* hist  = sm + 16896;
    int*      eq    = (int*)(sm + 17160);
    int*      ctr   = (int*)(sm + 17224);

    const int tid = threadIdx.x;
    const int lane = tid & 31;
    const int r = blockIdx.x;
    const size_t base = (size_t)r * D_HID;

    for (int j = tid; j < D_HID; j += 256) keys[j] = f2key(g_pre[base + j]);
    for (int w = tid; w < D_HID / 32; w += 256) deadb[w] = g_deadbits[w];
    __syncthreads();

    uint32_t T; int needEq;
    radix_select(keys, deadb, false, hist, 96, &T, &needEq, lane);
    if (tid == 0) ctr[0] = 0;
    __syncthreads();
    for (int j = tid; j < D_HID; j += 256) {
        z_out[base + j] = 0.f;
        if (keys[j] >= T) {
            int p = atomicAdd(&ctr[0], 1);
            if (p < NCAND) g_cand[(size_t)r * NCAND + p] = j;
        }
    }
    __syncthreads();
    if (tid == 0) g_cand_n[r] = min(ctr[0], NCAND);
    __syncthreads();

    uint32_t Ta; int needEqA;
    radix_select(keys, deadb, true, hist, KAUX, &Ta, &needEqA, lane);
    if (tid == 0) { ctr[0] = 0; ctr[1] = 0; }
    __syncthreads();
    for (int j = tid; j < D_HID; j += 256) {
        uint32_t k = ((deadb[j >> 5] >> (j & 31)) & 1u) ? keys[j] : 0u;
        if (k != 0u && k == Ta) { int p = atomicAdd(&ctr[1], 1); if (p < 64) eq[p] = j; }
    }
    __syncthreads();
    if (tid == 0) {
        int m = min(ctr[1], 64);
        int take = min(needEqA, m);
        for (int a = 0; a < take; ++a) {
            int best = a;
            for (int b = a + 1; b < m; ++b) if (eq[b] < eq[best]) best = b;
            int t2 = eq[a]; eq[a] = eq[best]; eq[best] = t2;
        }
        ctr[1] = take;
    }
    __syncthreads();
    const int nEqA = ctr[1];
    for (int j = tid; j < D_HID; j += 256) {
        uint32_t k = ((deadb[j >> 5] >> (j & 31)) & 1u) ? keys[j] : 0u;
        bool sel = (k > Ta);
        if (!sel && k != 0u && k == Ta)
            for (int a = 0; a < nEqA; ++a) if (eq[a] == j) { sel = true; break; }
        if (sel) {
            int p = atomicAdd(&ctr[0], 1);
            if (p < KAUX) { g_aux_idx[(size_t)r * KAUX + p] = j; g_aux_val[(size_t)r * KAUX + p] = key2f(keys[j]); }
        }
    }
    __syncthreads();
    if (tid == 0)
        for (int p = min(ctr[0], KAUX); p < KAUX; ++p) {
            g_aux_idx[(size_t)r * KAUX + p] = 0; g_aux_val[(size_t)r * KAUX + p] = -1.f;
        }
}

// ---------------- exact-Eigen refine (kc=248 panel folds, bitwise-ref values) -------
__global__ __launch_bounds__(128) void refine_kernel(
    const float* __restrict__ X, const float* __restrict__ WE,
    const float* __restrict__ be, const float* __restrict__ bd,
    float* __restrict__ z_out)
{
    __shared__ __align__(16) float xs[D_IN];
    __shared__ float vals[NCAND];
    __shared__ int   idxs[NCAND];
    __shared__ int   l0c;
    const int tid = threadIdx.x, r = blockIdx.x;
    if (tid == 0) l0c = 0;
    for (int k = tid; k < D_IN; k += 128)
        xs[k] = X[(size_t)r * D_IN + k] - bd[k];
    const int n = g_cand_n[r];
    if (tid < n) idxs[tid] = g_cand[(size_t)r * NCAND + tid];
    __syncthreads();

    if (tid < n) {
        const int fi = idxs[tid];
        const float4* w4 = (const float4*)(WE + (size_t)fi * D_IN);
        float acc = 0.f, pan = 0.f;
        int next = 248;
        for (int k = 0; k < D_IN; k += 4) {
            if (k == next) { acc += pan; pan = 0.f; next += 248; }
            float4 w = w4[k >> 2];
            pan = fmaf(xs[k + 0], w.x, pan);
            pan = fmaf(xs[k + 1], w.y, pan);
            pan = fmaf(xs[k + 2], w.z, pan);
            pan = fmaf(xs[k + 3], w.w, pan);
        }
        acc += pan;
        vals[tid] = acc + be[fi];
    }
    __syncthreads();

    if (tid < n) {
        const float v = vals[tid];
        const int myi = idxs[tid];
        int rank = 0;
        for (int j = 0; j < n; ++j) {
            const float u = vals[j];
            if (u > v || (u == v && idxs[j] < myi)) ++rank;
        }
        if (rank < KSEL) {
            g_sel_idx[r * KSEL + rank] = myi;
            g_sel_val[r * KSEL + rank] = v;
            z_out[(size_t)r * D_HID + myi] = fmaxf(v, 0.f);
            if (v > 0.f) atomicAdd(&l0c, 1);
        }
    }
    __syncthreads();
    if (tid == 0) g_l0_p[r] = (float)l0c;
}

// ---------------- sparse decode main (fp32 weights) ----------------
__global__ __launch_bounds__(256) void decode_main(const float* __restrict__ X,
                                                   float* __restrict__ xhat,
                                                   const float* __restrict__ bd)
{
    __shared__ int s_idx[KSEL];
    __shared__ float s_val[KSEL];
    __shared__ float red[8];
    const int tid = threadIdx.x, r = blockIdx.x;
    if (tid < KSEL) {
        s_idx[tid] = g_sel_idx[r * KSEL + tid];
        s_val[tid] = fmaxf(g_sel_val[r * KSEL + tid], 0.f);
    }
    __syncthreads();
    const float4* bd4 = (const float4*)bd;
    float4 acc0 = bd4[tid], acc1 = bd4[tid + 256];
    #pragma unroll 4
    for (int s = 0; s < KSEL; ++s) {
        float v = s_val[s];
        const float4* w = (const float4*)(g_WT + (size_t)s_idx[s] * D_IN);
        float4 w0 = w[tid], w1 = w[tid + 256];
        acc0.x += v * w0.x; acc0.y += v * w0.y; acc0.z += v * w0.z; acc0.w += v * w0.w;
        acc1.x += v * w1.x; acc1.y += v * w1.y; acc1.z += v * w1.z; acc1.w += v * w1.w;
    }
    const size_t b4 = (size_t)r * (D_IN / 4);
    ((float4*)xhat)[b4 + tid] = acc0;
    ((float4*)xhat)[b4 + tid + 256] = acc1;
    const float4* X4 = (const float4*)X;
    float4 x0 = X4[b4 + tid], x1 = X4[b4 + tid + 256];
    float d, loc = 0.f;
    d = acc0.x - x0.x; loc += d * d;  d = acc0.y - x0.y; loc += d * d;
    d = acc0.z - x0.z; loc += d * d;  d = acc0.w - x0.w; loc += d * d;
    d = acc1.x - x1.x; loc += d * d;  d = acc1.y - x1.y; loc += d * d;
    d = acc1.z - x1.z; loc += d * d;  d = acc1.w - x1.w; loc += d * d;
    #pragma unroll
    for (int o = 16; o; o >>= 1) loc += __shfl_down_sync(0xFFFFFFFFu, loc, o);
    if ((tid & 31) == 0) red[tid >> 5] = loc;
    __syncthreads();
    if (tid == 0) {
        float s = 0.f;
        for (int w2 = 0; w2 < 8; ++w2) s += red[w2];
        g_recon_p[r] = s;
    }
}

// ---------------- aux decode (bf16 weights) ----------------
__global__ __launch_bounds__(256) void decode_aux(const float* __restrict__ X,
                                                  const float* __restrict__ xhat)
{
    __shared__ int s_idx[KAUX];
    __shared__ float s_val[KAUX];
    __shared__ float red[8];
    const int tid = threadIdx.x, r = blockIdx.x;
    for (int s = tid; s < KAUX; s += 256) {
        s_idx[s] = g_aux_idx[(size_t)r * KAUX + s];
        s_val[s] = fmaxf(g_aux_val[(size_t)r * KAUX + s], 0.f);
    }
    __syncthreads();
    float acc[8];
    #pragma unroll
    for (int e = 0; e < 8; ++e) acc[e] = 0.f;
    #pragma unroll 2
    for (int s = 0; s < KAUX; ++s) {
        float v = s_val[s];
        uint4 w = *((const uint4*)(g_WTh + (size_t)s_idx[s] * (D_IN / 2)) + tid);
        float2 f0 = __bfloat1622float2(*reinterpret_cast<__nv_bfloat162*>(&w.x));
        float2 f1 = __bfloat1622float2(*reinterpret_cast<__nv_bfloat162*>(&w.y));
        float2 f2 = __bfloat1622float2(*reinterpret_cast<__nv_bfloat162*>(&w.z));
        float2 f3 = __bfloat1622float2(*reinterpret_cast<__nv_bfloat162*>(&w.w));
        acc[0] = fmaf(v, f0.x, acc[0]); acc[1] = fmaf(v, f0.y, acc[1]);
        acc[2] = fmaf(v, f1.x, acc[2]); acc[3] = fmaf(v, f1.y, acc[3]);
        acc[4] = fmaf(v, f2.x, acc[4]); acc[5] = fmaf(v, f2.y, acc[5]);
        acc[6] = fmaf(v, f3.x, acc[6]); acc[7] = fmaf(v, f3.y, acc[7]);
    }
    const size_t b4 = (size_t)r * (D_IN / 4) + tid * 2;
    const float4* X4 = (const float4*)X;
    const float4* H4 = (const float4*)xhat;
    float4 x0 = X4[b4], x1 = X4[b4 + 1];
    float4 h0 = H4[b4], h1 = H4[b4 + 1];
    float d, loc = 0.f;
    d = acc[0] - (x0.x - h0.x); loc += d * d;  d = acc[1] - (x0.y - h0.y); loc += d * d;
    d = acc[2] - (x0.z - h0.z); loc += d * d;  d = acc[3] - (x0.w - h0.w); loc += d * d;
    d = acc[4] - (x1.x - h1.x); loc += d * d;  d = acc[5] - (x1.y - h1.y); loc += d * d;
    d = acc[6] - (x1.z - h1.z); loc += d * d;  d = acc[7] - (x1.w - h1.w); loc += d * d;
    #pragma unroll
    for (int o = 16; o; o >>= 1) loc += __shfl_down_sync(0xFFFFFFFFu, loc, o);
    if ((tid & 31) == 0) red[tid >> 5] = loc;
    __syncthreads();
    if (tid == 0) {
        float s = 0.f;
        for (int w2 = 0; w2 < 8; ++w2) s += red[w2];
        g_aux_p[r] = s;
    }
}

// ---------------- final scalar reduction ----------------
__global__ void finalize_kernel(float* __restrict__ outs)
{
    __shared__ double sd[256];
    const int tid = threadIdx.x;
    double s = 0.0;
    for (int i = tid; i < BATCH; i += 256) s += (double)g_recon_p[i];
    sd[tid] = s; __syncthreads();
    for (int o = 128; o > 0; o >>= 1) { if (tid < o) sd[tid] += sd[tid + o]; __syncthreads(); }
    double recon = sd[0] / ((double)BATCH * (double)D_IN);
    __syncthreads();

    s = 0.0;
    for (int i = tid; i < BATCH; i += 256) s += (double)g_aux_p[i];
    sd[tid] = s; __syncthreads();
    for (int o = 128; o > 0; o >>= 1) { if (tid < o) sd[tid] += sd[tid + o]; __syncthreads(); }
    double aux = sd[0] / ((double)BATCH * (double)D_IN);
    __syncthreads();

    s = 0.0;
    for (int i = tid; i < BATCH; i += 256) s += (double)g_l0_p[i];
    sd[tid] = s; __syncthreads();
    for (int o = 128; o > 0; o >>= 1) { if (tid < o) sd[tid] += sd[tid + o]; __syncthreads(); }
    double l0 = sd[0] / (double)BATCH;

    if (tid == 0) {
        outs[0] = (float)(recon + aux * (1.0 / 32.0));
        outs[1] = (float)recon;
        outs[2] = (float)aux;
        outs[3] = (float)l0;
    }
}

// ---------------- launch ----------------
extern "C" void kernel_launch(void* const* d_in, const int* in_sizes, int n_in,
                              void* d_out, int out_size) {
    (void)in_sizes; (void)n_in; (void)out_size;
    const float* X  = (const float*)d_in[0];
    const float* WE = (const float*)d_in[1];
    const float* be = (const float*)d_in[2];
    const float* WD = (const float*)d_in[3];
    const float* bd = (const float*)d_in[4];
    const uint8_t* dm = (const uint8_t*)d_in[5];

    float* out = (float*)d_out;
    float* xhat = out;
    float* z = out + (size_t)BATCH * D_IN;
    float* scalars = z + (size_t)BATCH * D_HID;

    cudaFuncSetAttribute(topk_kernel, cudaFuncAttributeMaxDynamicSharedMemorySize, 70 * 1024);
    cudaFuncSetAttribute(encoder_mma, cudaFuncAttributeMaxDynamicSharedMemorySize, 2 * STAGEB);

    prep_mask<<<1, 512>>>(dm);
    transpose_wdec<<<dim3(D_HID / 32, D_IN / 32), dim3(32, 8)>>>(WD);
    convert_wdec_bf16<<<(unsigned)(((size_t)D_HID * D_IN / 2 + 255) / 256), 256>>>();
    split_x<<<(unsigned)(((size_t)BATCH * D_IN / 4 + 255) / 256), 256>>>(X, bd);
    split_w<<<(unsigned)(((size_t)D_HID * D_IN / 4 + 255) / 256), 256>>>(WE);
    encoder_mma<<<dim3(BATCH / ENC_BM, D_HID / ENC_BN), 256, 2 * STAGEB>>>(be);
    topk_kernel<<<BATCH, 256, 70 * 1024>>>(z);
    refine_kernel<<<BATCH, 128>>>(X, WE, be, bd, z);
    decode_main<<<BATCH, 256>>>(X, xhat, bd);
    decode_aux<<<BATCH, 256>>>(X, xhat);
    finalize_kernel<<<1, 256>>>(scalars);
}